// round 1
// baseline (speedup 1.0000x reference)
#include <cuda_runtime.h>
#include <cstdint>

// Problem constants
#define PB  8
#define PS  1024
#define PH  768
#define PNH 12
#define PDH 64
#define PM  (PB * PS)          // 8192 rows
#define PELEMS (PB * PS * PH)  // 6291456

// ---------------------------------------------------------------------------
// Scratch (static device globals — no allocation)
// ---------------------------------------------------------------------------
__device__ float g_q [PELEMS];
__device__ float g_k [PELEMS];
__device__ float g_v [PELEMS];
__device__ float g_qd[PELEMS];
__device__ float g_kd[PELEMS];
__device__ float g_vd[PELEMS];
__device__ float g_cx[PELEMS];
__device__ float g_cy[PELEMS];

// ---------------------------------------------------------------------------
// GEMM: C[M,N] = A[M,K] @ W[N,K]^T + bscale * bias[N]
// bscale = (*s1 + *s2) if s1 != nullptr else 1.0
// Tiles: 64x64x16, 256 threads, 4x4 microtile per thread.
// ---------------------------------------------------------------------------
__global__ void gemm_bias_kernel(const float* __restrict__ A,
                                 const float* __restrict__ W,
                                 const float* __restrict__ bias,
                                 const float* __restrict__ s1,
                                 const float* __restrict__ s2,
                                 float* __restrict__ C,
                                 int M, int N, int K)
{
    __shared__ float As[16][65];
    __shared__ float Bs[16][65];

    const int tid = threadIdx.x;
    const int tx  = tid & 15;
    const int ty  = tid >> 4;
    const int row0 = blockIdx.y * 64;
    const int col0 = blockIdx.x * 64;

    const float* Ab = A + (size_t)row0 * K;
    const float* Wb = W + (size_t)col0 * K;

    const int lr = tid >> 2;        // 0..63 (tile row)
    const int lc = (tid & 3) * 4;   // 0,4,8,12 (k offset)

    float acc[4][4] = {};

    for (int k0 = 0; k0 < K; k0 += 16) {
        float4 a4 = *(const float4*)(Ab + (size_t)lr * K + k0 + lc);
        float4 w4 = *(const float4*)(Wb + (size_t)lr * K + k0 + lc);
        As[lc + 0][lr] = a4.x; As[lc + 1][lr] = a4.y;
        As[lc + 2][lr] = a4.z; As[lc + 3][lr] = a4.w;
        Bs[lc + 0][lr] = w4.x; Bs[lc + 1][lr] = w4.y;
        Bs[lc + 2][lr] = w4.z; Bs[lc + 3][lr] = w4.w;
        __syncthreads();

        #pragma unroll
        for (int kk = 0; kk < 16; kk++) {
            float av[4], wv[4];
            #pragma unroll
            for (int i = 0; i < 4; i++) av[i] = As[kk][ty * 4 + i];
            #pragma unroll
            for (int j = 0; j < 4; j++) wv[j] = Bs[kk][tx * 4 + j];
            #pragma unroll
            for (int i = 0; i < 4; i++)
                #pragma unroll
                for (int j = 0; j < 4; j++)
                    acc[i][j] = fmaf(av[i], wv[j], acc[i][j]);
        }
        __syncthreads();
    }

    float bscale = 1.0f;
    if (s1) bscale = *s1 + *s2;

    #pragma unroll
    for (int i = 0; i < 4; i++) {
        const int r = row0 + ty * 4 + i;
        #pragma unroll
        for (int j = 0; j < 4; j++) {
            const int c = col0 + tx * 4 + j;
            C[(size_t)r * N + c] = acc[i][j] + bscale * bias[c];
        }
    }
}

// ---------------------------------------------------------------------------
// Flash attention over one KV stream (64-query tile x full S keys).
// 256 threads; thread (tx,ty) owns rows ty*4+{0..3}, cols/dims tx*4+{0..3}.
// ---------------------------------------------------------------------------
__device__ __forceinline__ void flash_stream(
    const float* __restrict__ Kg, const float* __restrict__ Vg,
    int b, int h,
    float (*Qs)[65], float (*Ks)[65], float (*Vs)[65], float (*Ps)[65],
    float o[4][4], int tx, int ty, int tid)
{
    float m[4], l[4];
    #pragma unroll
    for (int i = 0; i < 4; i++) {
        m[i] = -1e30f; l[i] = 0.0f;
        #pragma unroll
        for (int j = 0; j < 4; j++) o[i][j] = 0.0f;
    }

    for (int kt = 0; kt < PS / 64; kt++) {
        __syncthreads();   // previous tile fully consumed
        // Load K/V tiles (64x64 each), float4 per thread chunk
        for (int i = tid; i < 64 * 16; i += 256) {
            const int r = i >> 4;
            const int c = (i & 15) << 2;
            const size_t gidx = (size_t)(b * PS + kt * 64 + r) * PH + h * PDH + c;
            const float4 k4 = *(const float4*)(Kg + gidx);
            Ks[r][c + 0] = k4.x; Ks[r][c + 1] = k4.y;
            Ks[r][c + 2] = k4.z; Ks[r][c + 3] = k4.w;
            const float4 v4 = *(const float4*)(Vg + gidx);
            Vs[r][c + 0] = v4.x; Vs[r][c + 1] = v4.y;
            Vs[r][c + 2] = v4.z; Vs[r][c + 3] = v4.w;
        }
        __syncthreads();

        // Scores: S = Q @ K^T  (4x4 microtile per thread)
        float s[4][4] = {};
        #pragma unroll 8
        for (int d = 0; d < PDH; d++) {
            float qv[4], kv[4];
            #pragma unroll
            for (int i = 0; i < 4; i++) qv[i] = Qs[ty * 4 + i][d];
            #pragma unroll
            for (int j = 0; j < 4; j++) kv[j] = Ks[tx * 4 + j][d];
            #pragma unroll
            for (int i = 0; i < 4; i++)
                #pragma unroll
                for (int j = 0; j < 4; j++)
                    s[i][j] = fmaf(qv[i], kv[j], s[i][j]);
        }

        const float scale = 0.125f;  // 1/sqrt(64)
        #pragma unroll
        for (int i = 0; i < 4; i++) {
            float mx = -1e30f;
            #pragma unroll
            for (int j = 0; j < 4; j++) {
                s[i][j] *= scale;
                mx = fmaxf(mx, s[i][j]);
            }
            // row reduce across the 16 lanes sharing this row group
            mx = fmaxf(mx, __shfl_xor_sync(0xffffffffu, mx, 1));
            mx = fmaxf(mx, __shfl_xor_sync(0xffffffffu, mx, 2));
            mx = fmaxf(mx, __shfl_xor_sync(0xffffffffu, mx, 4));
            mx = fmaxf(mx, __shfl_xor_sync(0xffffffffu, mx, 8));

            const float mn   = fmaxf(m[i], mx);
            const float corr = __expf(m[i] - mn);
            float rs = 0.0f;
            #pragma unroll
            for (int j = 0; j < 4; j++) {
                s[i][j] = __expf(s[i][j] - mn);
                rs += s[i][j];
            }
            rs += __shfl_xor_sync(0xffffffffu, rs, 1);
            rs += __shfl_xor_sync(0xffffffffu, rs, 2);
            rs += __shfl_xor_sync(0xffffffffu, rs, 4);
            rs += __shfl_xor_sync(0xffffffffu, rs, 8);

            l[i] = l[i] * corr + rs;
            m[i] = mn;
            #pragma unroll
            for (int j = 0; j < 4; j++) o[i][j] *= corr;
            #pragma unroll
            for (int j = 0; j < 4; j++) Ps[ty * 4 + i][tx * 4 + j] = s[i][j];
        }
        __syncthreads();

        // O += P @ V
        #pragma unroll 4
        for (int k = 0; k < 64; k++) {
            float vv[4];
            #pragma unroll
            for (int j = 0; j < 4; j++) vv[j] = Vs[k][tx * 4 + j];
            #pragma unroll
            for (int i = 0; i < 4; i++) {
                const float p = Ps[ty * 4 + i][k];
                #pragma unroll
                for (int j = 0; j < 4; j++)
                    o[i][j] = fmaf(p, vv[j], o[i][j]);
            }
        }
    }

    #pragma unroll
    for (int i = 0; i < 4; i++) {
        const float inv = 1.0f / l[i];
        #pragma unroll
        for (int j = 0; j < 4; j++) o[i][j] *= inv;
    }
}

// Dual-stream attention: ctx = w1*attend(Q,K1,V1) + w2*attend(Q,K2,V2)
__global__ void attn_kernel(const float* __restrict__ Q,
                            const float* __restrict__ K1, const float* __restrict__ V1,
                            const float* __restrict__ K2, const float* __restrict__ V2,
                            const float* __restrict__ w1p, const float* __restrict__ w2p,
                            float* __restrict__ ctx)
{
    extern __shared__ float smem[];
    float (*Qs)[65] = (float(*)[65])(smem);
    float (*Ks)[65] = (float(*)[65])(smem + 64 * 65);
    float (*Vs)[65] = (float(*)[65])(smem + 2 * 64 * 65);
    float (*Ps)[65] = (float(*)[65])(smem + 3 * 64 * 65);

    const int qt = blockIdx.x;
    const int h  = blockIdx.y;
    const int b  = blockIdx.z;
    const int tid = threadIdx.x;
    const int tx  = tid & 15;
    const int ty  = tid >> 4;

    // Load Q tile once
    for (int i = tid; i < 64 * 16; i += 256) {
        const int r = i >> 4;
        const int c = (i & 15) << 2;
        const float4 q4 = *(const float4*)(Q + (size_t)(b * PS + qt * 64 + r) * PH + h * PDH + c);
        Qs[r][c + 0] = q4.x; Qs[r][c + 1] = q4.y;
        Qs[r][c + 2] = q4.z; Qs[r][c + 3] = q4.w;
    }
    // flash_stream begins with __syncthreads()

    float o1[4][4], o2[4][4];
    flash_stream(K1, V1, b, h, Qs, Ks, Vs, Ps, o1, tx, ty, tid);
    flash_stream(K2, V2, b, h, Qs, Ks, Vs, Ps, o2, tx, ty, tid);

    const float w1 = *w1p;
    const float w2 = *w2p;
    #pragma unroll
    for (int i = 0; i < 4; i++) {
        const int r = qt * 64 + ty * 4 + i;
        #pragma unroll
        for (int j = 0; j < 4; j++) {
            ctx[(size_t)(b * PS + r) * PH + h * PDH + tx * 4 + j] =
                w1 * o1[i][j] + w2 * o2[i][j];
        }
    }
}

// ---------------------------------------------------------------------------
// Launch
// ---------------------------------------------------------------------------
extern "C" void kernel_launch(void* const* d_in, const int* in_sizes, int n_in,
                              void* d_out, int out_size)
{
    const float* hx  = (const float*)d_in[0];
    const float* hy  = (const float*)d_in[1];
    const float* Wq  = (const float*)d_in[2];  const float* bq  = (const float*)d_in[3];
    const float* Wk  = (const float*)d_in[4];  const float* bk  = (const float*)d_in[5];
    const float* Wv  = (const float*)d_in[6];  const float* bv  = (const float*)d_in[7];
    const float* Wo  = (const float*)d_in[8];  const float* bo  = (const float*)d_in[9];
    const float* Wqd = (const float*)d_in[10]; const float* bqd = (const float*)d_in[11];
    const float* Wkd = (const float*)d_in[12]; const float* bkd = (const float*)d_in[13];
    const float* Wvd = (const float*)d_in[14]; const float* bvd = (const float*)d_in[15];
    const float* w11 = (const float*)d_in[16 + 2]; // placeholder, fixed below
    (void)w11;

    const float* pw11 = (const float*)d_in[18];
    const float* pw12 = (const float*)d_in[19];
    const float* pw21 = (const float*)d_in[20];
    const float* pw22 = (const float*)d_in[21];
    const float* Wod  = (const float*)d_in[16];
    const float* bod  = (const float*)d_in[17];

    float* out = (float*)d_out;

    float *q, *k, *v, *qd, *kd, *vd, *cx, *cy;
    cudaGetSymbolAddress((void**)&q,  g_q);
    cudaGetSymbolAddress((void**)&k,  g_k);
    cudaGetSymbolAddress((void**)&v,  g_v);
    cudaGetSymbolAddress((void**)&qd, g_qd);
    cudaGetSymbolAddress((void**)&kd, g_kd);
    cudaGetSymbolAddress((void**)&vd, g_vd);
    cudaGetSymbolAddress((void**)&cx, g_cx);
    cudaGetSymbolAddress((void**)&cy, g_cy);

    const dim3 gg(PH / 64, PM / 64);

    // QKV projections (both streams)
    gemm_bias_kernel<<<gg, 256>>>(hx, Wq,  bq,  nullptr, nullptr, q,  PM, PH, PH);
    gemm_bias_kernel<<<gg, 256>>>(hx, Wk,  bk,  nullptr, nullptr, k,  PM, PH, PH);
    gemm_bias_kernel<<<gg, 256>>>(hx, Wv,  bv,  nullptr, nullptr, v,  PM, PH, PH);
    gemm_bias_kernel<<<gg, 256>>>(hy, Wqd, bqd, nullptr, nullptr, qd, PM, PH, PH);
    gemm_bias_kernel<<<gg, 256>>>(hy, Wkd, bkd, nullptr, nullptr, kd, PM, PH, PH);
    gemm_bias_kernel<<<gg, 256>>>(hy, Wvd, bvd, nullptr, nullptr, vd, PM, PH, PH);

    // Dual-stream flash attention
    const size_t att_smem = 4 * 64 * 65 * sizeof(float);  // 66,560 B
    cudaFuncSetAttribute(attn_kernel,
                         cudaFuncAttributeMaxDynamicSharedMemorySize, (int)att_smem);
    const dim3 ga(PS / 64, PNH, PB);
    // attention_sx: w11*attend(q,k,v) + w12*attend(q,kd,vd)
    attn_kernel<<<ga, 256, att_smem>>>(q,  k,  v,  kd, vd, pw11, pw12, cx);
    // attention_sy: w21*attend(qd,kd,vd) + w22*attend(qd,k,v)
    attn_kernel<<<ga, 256, att_smem>>>(qd, kd, vd, k,  v,  pw21, pw22, cy);

    // Output projections with folded bias scale (w1+w2)*b
    gemm_bias_kernel<<<gg, 256>>>(cx, Wo,  bo,  pw11, pw12, out,                       PM, PH, PH);
    gemm_bias_kernel<<<gg, 256>>>(cy, Wod, bod, pw21, pw22, out + (size_t)PM * PH,     PM, PH, PH);
}

// round 4
// speedup vs baseline: 3.4312x; 3.4312x over previous
#include <cuda_runtime.h>
#include <cuda_bf16.h>
#include <cstdint>

// Problem constants
#define PB  8
#define PS  1024
#define PH  768
#define PNH 12
#define PDH 64
#define PM  (PB * PS)          // 8192
#define PELEMS (PM * PH)       // 6291456
#define WN  (PH * PH)          // 589824

// ---------------------------------------------------------------------------
// Scratch (static device globals — no allocation)
// ---------------------------------------------------------------------------
__device__ __nv_bfloat16 g_xhi [PELEMS], g_xlo [PELEMS];
__device__ __nv_bfloat16 g_yhi [PELEMS], g_ylo [PELEMS];
__device__ __nv_bfloat16 g_qhi [PELEMS], g_qlo [PELEMS];
__device__ __nv_bfloat16 g_khi [PELEMS], g_klo [PELEMS];
__device__ __nv_bfloat16 g_vhi [PELEMS], g_vlo [PELEMS];
__device__ __nv_bfloat16 g_qdhi[PELEMS], g_qdlo[PELEMS];
__device__ __nv_bfloat16 g_kdhi[PELEMS], g_kdlo[PELEMS];
__device__ __nv_bfloat16 g_vdhi[PELEMS], g_vdlo[PELEMS];
__device__ __nv_bfloat16 g_cxhi[PELEMS], g_cxlo[PELEMS];
__device__ __nv_bfloat16 g_cyhi[PELEMS], g_cylo[PELEMS];
__device__ __nv_bfloat16 g_whi [8 * WN], g_wlo [8 * WN];

// ---------------------------------------------------------------------------
// Helpers (sm_80+-portable: ldmatrix + mma.sync + cp.async only)
// ---------------------------------------------------------------------------
__device__ __forceinline__ uint32_t smem_u32(const void* p) {
    uint32_t a;
    asm("{ .reg .u64 t; cvta.to.shared.u64 t, %1; cvt.u32.u64 %0, t; }"
        : "=r"(a) : "l"(p));
    return a;
}

__device__ __forceinline__ void cpasync16(uint32_t dst, const void* src) {
    asm volatile("cp.async.cg.shared.global [%0], [%1], 16;"
                 :: "r"(dst), "l"(src));
}
#define CP_COMMIT() asm volatile("cp.async.commit_group;")
#define CP_WAIT(n)  asm volatile("cp.async.wait_group %0;" :: "n"(n))

__device__ __forceinline__ void ldm4(uint32_t r[4], uint32_t addr) {
    asm volatile("ldmatrix.sync.aligned.m8n8.x4.shared.b16 {%0,%1,%2,%3}, [%4];"
        : "=r"(r[0]), "=r"(r[1]), "=r"(r[2]), "=r"(r[3]) : "r"(addr));
}
__device__ __forceinline__ void ldm4t(uint32_t r[4], uint32_t addr) {
    asm volatile("ldmatrix.sync.aligned.m8n8.x4.trans.shared.b16 {%0,%1,%2,%3}, [%4];"
        : "=r"(r[0]), "=r"(r[1]), "=r"(r[2]), "=r"(r[3]) : "r"(addr));
}

__device__ __forceinline__ void mma16816(float c[4], const uint32_t a[4],
                                         const uint32_t b[2]) {
    asm volatile("mma.sync.aligned.m16n8k16.row.col.f32.bf16.bf16.f32 "
        "{%0,%1,%2,%3}, {%4,%5,%6,%7}, {%8,%9}, {%0,%1,%2,%3};"
        : "+f"(c[0]), "+f"(c[1]), "+f"(c[2]), "+f"(c[3])
        : "r"(a[0]), "r"(a[1]), "r"(a[2]), "r"(a[3]), "r"(b[0]), "r"(b[1]));
}

__device__ __forceinline__ uint32_t packbf(__nv_bfloat16 a, __nv_bfloat16 b) {
    __nv_bfloat162 t(a, b);
    return *(uint32_t*)&t;
}

// ---------------------------------------------------------------------------
// fp32 -> bf16 hi/lo split
// ---------------------------------------------------------------------------
__global__ void split_bf16(const float* __restrict__ x,
                           __nv_bfloat16* __restrict__ hi,
                           __nv_bfloat16* __restrict__ lo, int n4)
{
    int i = blockIdx.x * blockDim.x + threadIdx.x;
    if (i >= n4) return;
    float4 v = *(const float4*)(x + (size_t)i * 4);
    __nv_bfloat16 h0 = __float2bfloat16(v.x);
    __nv_bfloat16 h1 = __float2bfloat16(v.y);
    __nv_bfloat16 h2 = __float2bfloat16(v.z);
    __nv_bfloat16 h3 = __float2bfloat16(v.w);
    ((__nv_bfloat162*)hi)[i * 2 + 0] = __nv_bfloat162(h0, h1);
    ((__nv_bfloat162*)hi)[i * 2 + 1] = __nv_bfloat162(h2, h3);
    ((__nv_bfloat162*)lo)[i * 2 + 0] = __nv_bfloat162(
        __float2bfloat16(v.x - __bfloat162float(h0)),
        __float2bfloat16(v.y - __bfloat162float(h1)));
    ((__nv_bfloat162*)lo)[i * 2 + 1] = __nv_bfloat162(
        __float2bfloat16(v.z - __bfloat162float(h2)),
        __float2bfloat16(v.w - __bfloat162float(h3)));
}

// ---------------------------------------------------------------------------
// Split-bf16 GEMM on mma.sync: C[M,N] = A[M,K] @ W[N,K]^T + bscale*bias
// CTA tile 128x128, K-chunk 32, cp.async double-buffered. 256 threads.
// Outputs fp32 (Cf) and/or hi/lo bf16 planes (Chi/Clo).
// ---------------------------------------------------------------------------
#define GBK   32
#define GKCH  (PH / GBK)       // 24
#define GSA   40               // smem row stride in bf16 (80B)
#define PLANE_B (128 * GSA * 2)  // 10240
#define STAGE_B (4 * PLANE_B)    // 40960
#define GEMM_SMEM (2 * STAGE_B)  // 81920

__global__ void __launch_bounds__(256)
mm_gemm(const __nv_bfloat16* __restrict__ Ahi, const __nv_bfloat16* __restrict__ Alo,
        const __nv_bfloat16* __restrict__ Whi, const __nv_bfloat16* __restrict__ Wlo,
        const float* __restrict__ bias,
        const float* __restrict__ s1, const float* __restrict__ s2,
        float* __restrict__ Cf,
        __nv_bfloat16* __restrict__ Chi, __nv_bfloat16* __restrict__ Clo)
{
    extern __shared__ char smem[];
    const uint32_t sb = smem_u32(smem);
    const int tid = threadIdx.x;
    const int wid = tid >> 5, lane = tid & 31;
    const int warpM = wid >> 2, warpN = wid & 3;
    const int row0 = blockIdx.y * 128, col0 = blockIdx.x * 128;

    const __nv_bfloat16* g0 = Ahi + (size_t)row0 * PH;
    const __nv_bfloat16* g1 = Alo + (size_t)row0 * PH;
    const __nv_bfloat16* g2 = Whi + (size_t)col0 * PH;
    const __nv_bfloat16* g3 = Wlo + (size_t)col0 * PH;

    float acc[4][4][4];
    #pragma unroll
    for (int mt = 0; mt < 4; mt++)
        #pragma unroll
        for (int nt = 0; nt < 4; nt++)
            #pragma unroll
            for (int c = 0; c < 4; c++) acc[mt][nt][c] = 0.0f;

    // fragment addressing constants
    const int arow  = warpM * 64 + (lane & 15);
    const int akh   = lane >> 4;
    const int bkey  = warpN * 32 + (lane & 7) + ((lane >> 4) << 3);
    const int bkh   = (lane >> 3) & 1;

#define G_LOAD(kc, st) do {                                                   \
    const uint32_t dbase = sb + (st) * STAGE_B;                               \
    _Pragma("unroll")                                                         \
    for (int j = 0; j < 2; j++) {                                             \
        const int cc = j * 256 + tid;                                         \
        const int r = cc >> 2, seg = cc & 3;                                  \
        const size_t go = (size_t)r * PH + (kc) * GBK + seg * 8;              \
        const uint32_t so = r * (GSA * 2) + seg * 16;                         \
        cpasync16(dbase + 0 * PLANE_B + so, g0 + go);                         \
        cpasync16(dbase + 1 * PLANE_B + so, g1 + go);                         \
        cpasync16(dbase + 2 * PLANE_B + so, g2 + go);                         \
        cpasync16(dbase + 3 * PLANE_B + so, g3 + go);                         \
    }                                                                         \
} while (0)

    G_LOAD(0, 0);
    CP_COMMIT();

    for (int kc = 0; kc < GKCH; kc++) {
        if (kc + 1 < GKCH) {
            G_LOAD(kc + 1, (kc + 1) & 1);
            CP_COMMIT();
            CP_WAIT(1);
        } else {
            CP_WAIT(0);
        }
        __syncthreads();

        const uint32_t stb = sb + (kc & 1) * STAGE_B;
        #pragma unroll
        for (int ks = 0; ks < 2; ks++) {
            uint32_t ahi[4][4], alo[4][4];
            #pragma unroll
            for (int mt = 0; mt < 4; mt++) {
                const uint32_t addr = stb + (arow + mt * 16) * (GSA * 2)
                                      + ks * 32 + akh * 16;
                ldm4(ahi[mt], addr);
                ldm4(alo[mt], addr + PLANE_B);
            }
            uint32_t bhi[4][2], blo[4][2];
            #pragma unroll
            for (int ntp = 0; ntp < 2; ntp++) {
                const uint32_t addr = stb + 2 * PLANE_B
                                      + (bkey + ntp * 16) * (GSA * 2)
                                      + ks * 32 + bkh * 16;
                uint32_t t[4];
                ldm4(t, addr);
                bhi[2 * ntp][0] = t[0]; bhi[2 * ntp][1] = t[1];
                bhi[2 * ntp + 1][0] = t[2]; bhi[2 * ntp + 1][1] = t[3];
                ldm4(t, addr + PLANE_B);
                blo[2 * ntp][0] = t[0]; blo[2 * ntp][1] = t[1];
                blo[2 * ntp + 1][0] = t[2]; blo[2 * ntp + 1][1] = t[3];
            }
            #pragma unroll
            for (int mt = 0; mt < 4; mt++)
                #pragma unroll
                for (int nt = 0; nt < 4; nt++) {
                    mma16816(acc[mt][nt], ahi[mt], bhi[nt]);
                    mma16816(acc[mt][nt], ahi[mt], blo[nt]);
                    mma16816(acc[mt][nt], alo[mt], bhi[nt]);
                }
        }
        __syncthreads();
    }

    // epilogue
    const int g = lane >> 2, tig = lane & 3;
    const float bscale = s1 ? (*s1 + *s2) : 1.0f;
    #pragma unroll
    for (int mt = 0; mt < 4; mt++) {
        const int r0 = row0 + warpM * 64 + mt * 16 + g;
        #pragma unroll
        for (int nt = 0; nt < 4; nt++) {
            const int col = col0 + warpN * 32 + nt * 8 + tig * 2;
            const float b0 = bscale * bias[col];
            const float b1 = bscale * bias[col + 1];
            const float v00 = acc[mt][nt][0] + b0, v01 = acc[mt][nt][1] + b1;
            const float v10 = acc[mt][nt][2] + b0, v11 = acc[mt][nt][3] + b1;
            if (Cf) {
                *(float2*)(Cf + (size_t)r0 * PH + col)       = make_float2(v00, v01);
                *(float2*)(Cf + (size_t)(r0 + 8) * PH + col) = make_float2(v10, v11);
            }
            if (Chi) {
                __nv_bfloat16 h00 = __float2bfloat16(v00), h01 = __float2bfloat16(v01);
                __nv_bfloat16 h10 = __float2bfloat16(v10), h11 = __float2bfloat16(v11);
                *(__nv_bfloat162*)(Chi + (size_t)r0 * PH + col) = __nv_bfloat162(h00, h01);
                *(__nv_bfloat162*)(Chi + (size_t)(r0 + 8) * PH + col) = __nv_bfloat162(h10, h11);
                *(__nv_bfloat162*)(Clo + (size_t)r0 * PH + col) = __nv_bfloat162(
                    __float2bfloat16(v00 - __bfloat162float(h00)),
                    __float2bfloat16(v01 - __bfloat162float(h01)));
                *(__nv_bfloat162*)(Clo + (size_t)(r0 + 8) * PH + col) = __nv_bfloat162(
                    __float2bfloat16(v10 - __bfloat162float(h10)),
                    __float2bfloat16(v11 - __bfloat162float(h11)));
            }
        }
    }
}

// ---------------------------------------------------------------------------
// Dual-stream flash attention on mma.sync.
// CTA = 64 q-rows x (b,h); 4 warps, each warp owns 16 q-rows.
// ctx = w1*attend(Q,K1,V1) + w2*attend(Q,K2,V2), emitted as bf16 hi/lo.
// ---------------------------------------------------------------------------
#define AST     72                    // bf16 row stride (144B)
#define ATILE_B (64 * AST * 2)        // 9216
#define ATT_SMEM (6 * ATILE_B)        // 55296  [qh][ql][kh][kl][vh][vl]

__global__ void __launch_bounds__(128)
attn_mma(const __nv_bfloat16* __restrict__ Qh,  const __nv_bfloat16* __restrict__ Ql,
         const __nv_bfloat16* __restrict__ K1h, const __nv_bfloat16* __restrict__ K1l,
         const __nv_bfloat16* __restrict__ V1h, const __nv_bfloat16* __restrict__ V1l,
         const __nv_bfloat16* __restrict__ K2h, const __nv_bfloat16* __restrict__ K2l,
         const __nv_bfloat16* __restrict__ V2h, const __nv_bfloat16* __restrict__ V2l,
         const float* __restrict__ w1p, const float* __restrict__ w2p,
         __nv_bfloat16* __restrict__ ctxh, __nv_bfloat16* __restrict__ ctxl)
{
    extern __shared__ char smem[];
    const uint32_t sb = smem_u32(smem);
    const uint32_t kh_s = sb + 2 * ATILE_B;
    const uint32_t vh_s = sb + 4 * ATILE_B;

    const int qt = blockIdx.x, h = blockIdx.y, b = blockIdx.z;
    const int tid = threadIdx.x, wid = tid >> 5, lane = tid & 31;
    const int g = lane >> 2, tig = lane & 3;

    // --- load Q tile (hi/lo) ---
    #pragma unroll
    for (int j = 0; j < 4; j++) {
        const int cc = j * 128 + tid;        // 512 chunks per plane
        const int r = cc >> 3, seg = cc & 7;
        const size_t go = (size_t)(b * PS + qt * 64 + r) * PH + h * PDH + seg * 8;
        const uint32_t so = r * (AST * 2) + seg * 16;
        *(uint4*)(smem + so)           = *(const uint4*)(Qh + go);
        *(uint4*)(smem + ATILE_B + so) = *(const uint4*)(Ql + go);
    }
    __syncthreads();

    // --- Q fragments (held in registers for both streams) ---
    uint32_t qfh[4][4], qfl[4][4];
    {
        const int qrow = wid * 16 + (lane & 15);
        const int khalf = lane >> 4;
        #pragma unroll
        for (int ks = 0; ks < 4; ks++) {
            const uint32_t addr = sb + qrow * (AST * 2) + ks * 32 + khalf * 16;
            ldm4(qfh[ks], addr);
            ldm4(qfl[ks], addr + ATILE_B);
        }
    }

    const int bkey = (lane & 7) + ((lane >> 4) << 3);   // QK B-frag lane row
    const int bkh  = (lane >> 3) & 1;
    const int vkey = (lane & 7) + (((lane >> 3) & 1) << 3);  // PV B-frag lane row
    const int vdh  = (lane >> 4) << 3;

    const float w1 = *w1p, w2 = *w2p;
    float ostash[8][4];

    for (int s = 0; s < 2; s++) {
        const __nv_bfloat16* Kh_ = s ? K2h : K1h;
        const __nv_bfloat16* Kl_ = s ? K2l : K1l;
        const __nv_bfloat16* Vh_ = s ? V2h : V1h;
        const __nv_bfloat16* Vl_ = s ? V2l : V1l;

        float m[2] = { -1e30f, -1e30f }, l[2] = { 0.0f, 0.0f };
        float oacc[8][4];
        #pragma unroll
        for (int nt = 0; nt < 8; nt++)
            #pragma unroll
            for (int c = 0; c < 4; c++) oacc[nt][c] = 0.0f;

        for (int kt = 0; kt < PS / 64; kt++) {
            __syncthreads();
            #pragma unroll
            for (int j = 0; j < 4; j++) {
                const int cc = j * 128 + tid;
                const int r = cc >> 3, seg = cc & 7;
                const size_t go = (size_t)(b * PS + kt * 64 + r) * PH + h * PDH + seg * 8;
                const uint32_t so = r * (AST * 2) + seg * 16;
                *(uint4*)(smem + 2 * ATILE_B + so) = *(const uint4*)(Kh_ + go);
                *(uint4*)(smem + 3 * ATILE_B + so) = *(const uint4*)(Kl_ + go);
                *(uint4*)(smem + 4 * ATILE_B + so) = *(const uint4*)(Vh_ + go);
                *(uint4*)(smem + 5 * ATILE_B + so) = *(const uint4*)(Vl_ + go);
            }
            __syncthreads();

            // --- scores S = Q @ K^T (split 3-mma) ---
            float sacc[8][4];
            #pragma unroll
            for (int nt = 0; nt < 8; nt++)
                #pragma unroll
                for (int c = 0; c < 4; c++) sacc[nt][c] = 0.0f;

            #pragma unroll
            for (int ks = 0; ks < 4; ks++) {
                #pragma unroll
                for (int ntp = 0; ntp < 4; ntp++) {
                    const uint32_t addr = kh_s + (ntp * 16 + bkey) * (AST * 2)
                                          + ks * 32 + bkh * 16;
                    uint32_t th[4], tl[4];
                    ldm4(th, addr);
                    ldm4(tl, addr + ATILE_B);
                    const uint32_t b0h[2] = { th[0], th[1] }, b1h[2] = { th[2], th[3] };
                    const uint32_t b0l[2] = { tl[0], tl[1] }, b1l[2] = { tl[2], tl[3] };
                    mma16816(sacc[2 * ntp],     qfh[ks], b0h);
                    mma16816(sacc[2 * ntp],     qfh[ks], b0l);
                    mma16816(sacc[2 * ntp],     qfl[ks], b0h);
                    mma16816(sacc[2 * ntp + 1], qfh[ks], b1h);
                    mma16816(sacc[2 * ntp + 1], qfh[ks], b1l);
                    mma16816(sacc[2 * ntp + 1], qfl[ks], b1h);
                }
            }

            // --- online softmax (rows g and g+8) ---
            #pragma unroll
            for (int nt = 0; nt < 8; nt++)
                #pragma unroll
                for (int c = 0; c < 4; c++) sacc[nt][c] *= 0.125f;

            #pragma unroll
            for (int half = 0; half < 2; half++) {
                float mx = -1e30f;
                #pragma unroll
                for (int nt = 0; nt < 8; nt++)
                    mx = fmaxf(mx, fmaxf(sacc[nt][2 * half], sacc[nt][2 * half + 1]));
                mx = fmaxf(mx, __shfl_xor_sync(0xffffffffu, mx, 1));
                mx = fmaxf(mx, __shfl_xor_sync(0xffffffffu, mx, 2));
                const float mn = fmaxf(m[half], mx);
                const float corr = __expf(m[half] - mn);
                m[half] = mn;
                float rs = 0.0f;
                #pragma unroll
                for (int nt = 0; nt < 8; nt++) {
                    const float p0 = __expf(sacc[nt][2 * half] - mn);
                    const float p1 = __expf(sacc[nt][2 * half + 1] - mn);
                    sacc[nt][2 * half] = p0;
                    sacc[nt][2 * half + 1] = p1;
                    rs += p0 + p1;
                }
                rs += __shfl_xor_sync(0xffffffffu, rs, 1);
                rs += __shfl_xor_sync(0xffffffffu, rs, 2);
                l[half] = l[half] * corr + rs;
                #pragma unroll
                for (int nt = 0; nt < 8; nt++) {
                    oacc[nt][2 * half]     *= corr;
                    oacc[nt][2 * half + 1] *= corr;
                }
            }

            // --- pack P into bf16 hi/lo A-fragments ---
            uint32_t ph[8][2], pl[8][2];
            #pragma unroll
            for (int nt = 0; nt < 8; nt++) {
                #pragma unroll
                for (int half = 0; half < 2; half++) {
                    const float p0 = sacc[nt][2 * half], p1 = sacc[nt][2 * half + 1];
                    const __nv_bfloat16 h0 = __float2bfloat16(p0);
                    const __nv_bfloat16 h1 = __float2bfloat16(p1);
                    ph[nt][half] = packbf(h0, h1);
                    pl[nt][half] = packbf(__float2bfloat16(p0 - __bfloat162float(h0)),
                                          __float2bfloat16(p1 - __bfloat162float(h1)));
                }
            }

            // --- O += P @ V (split 3-mma, V^T via trans ldmatrix) ---
            #pragma unroll
            for (int ks = 0; ks < 4; ks++) {
                const uint32_t pah[4] = { ph[2 * ks][0], ph[2 * ks][1],
                                          ph[2 * ks + 1][0], ph[2 * ks + 1][1] };
                const uint32_t pal[4] = { pl[2 * ks][0], pl[2 * ks][1],
                                          pl[2 * ks + 1][0], pl[2 * ks + 1][1] };
                #pragma unroll
                for (int dhp = 0; dhp < 4; dhp++) {
                    const uint32_t addr = vh_s + (ks * 16 + vkey) * (AST * 2)
                                          + (dhp * 16 + vdh) * 2;
                    uint32_t th[4], tl[4];
                    ldm4t(th, addr);
                    ldm4t(tl, addr + ATILE_B);
                    const uint32_t b0h[2] = { th[0], th[1] }, b1h[2] = { th[2], th[3] };
                    const uint32_t b0l[2] = { tl[0], tl[1] }, b1l[2] = { tl[2], tl[3] };
                    mma16816(oacc[2 * dhp],     pah, b0h);
                    mma16816(oacc[2 * dhp],     pah, b0l);
                    mma16816(oacc[2 * dhp],     pal, b0h);
                    mma16816(oacc[2 * dhp + 1], pah, b1h);
                    mma16816(oacc[2 * dhp + 1], pah, b1l);
                    mma16816(oacc[2 * dhp + 1], pal, b1h);
                }
            }
        }

        if (s == 0) {
            const float i0 = w1 / l[0], i1 = w1 / l[1];
            #pragma unroll
            for (int nt = 0; nt < 8; nt++) {
                ostash[nt][0] = oacc[nt][0] * i0;
                ostash[nt][1] = oacc[nt][1] * i0;
                ostash[nt][2] = oacc[nt][2] * i1;
                ostash[nt][3] = oacc[nt][3] * i1;
            }
        } else {
            const float i0 = w2 / l[0], i1 = w2 / l[1];
            const int r0 = qt * 64 + wid * 16 + g;
            #pragma unroll
            for (int nt = 0; nt < 8; nt++) {
                const int col = h * PDH + nt * 8 + tig * 2;
                const float v00 = ostash[nt][0] + oacc[nt][0] * i0;
                const float v01 = ostash[nt][1] + oacc[nt][1] * i0;
                const float v10 = ostash[nt][2] + oacc[nt][2] * i1;
                const float v11 = ostash[nt][3] + oacc[nt][3] * i1;
                const size_t o0 = (size_t)(b * PS + r0) * PH + col;
                const size_t o1 = (size_t)(b * PS + r0 + 8) * PH + col;
                const __nv_bfloat16 h00 = __float2bfloat16(v00);
                const __nv_bfloat16 h01 = __float2bfloat16(v01);
                const __nv_bfloat16 h10 = __float2bfloat16(v10);
                const __nv_bfloat16 h11 = __float2bfloat16(v11);
                *(__nv_bfloat162*)(ctxh + o0) = __nv_bfloat162(h00, h01);
                *(__nv_bfloat162*)(ctxh + o1) = __nv_bfloat162(h10, h11);
                *(__nv_bfloat162*)(ctxl + o0) = __nv_bfloat162(
                    __float2bfloat16(v00 - __bfloat162float(h00)),
                    __float2bfloat16(v01 - __bfloat162float(h01)));
                *(__nv_bfloat162*)(ctxl + o1) = __nv_bfloat162(
                    __float2bfloat16(v10 - __bfloat162float(h10)),
                    __float2bfloat16(v11 - __bfloat162float(h11)));
            }
        }
    }
}

// ---------------------------------------------------------------------------
// Launch
// ---------------------------------------------------------------------------
extern "C" void kernel_launch(void* const* d_in, const int* in_sizes, int n_in,
                              void* d_out, int out_size)
{
    const float* hx = (const float*)d_in[0];
    const float* hy = (const float*)d_in[1];
    const float* Wf[8] = { (const float*)d_in[2],  (const float*)d_in[4],
                           (const float*)d_in[6],  (const float*)d_in[8],
                           (const float*)d_in[10], (const float*)d_in[12],
                           (const float*)d_in[14], (const float*)d_in[16] };
    const float* Bf[8] = { (const float*)d_in[3],  (const float*)d_in[5],
                           (const float*)d_in[7],  (const float*)d_in[9],
                           (const float*)d_in[11], (const float*)d_in[13],
                           (const float*)d_in[15], (const float*)d_in[17] };
    // order: 0=q 1=k 2=v 3=o 4=qd 5=kd 6=vd 7=od
    const float* pw11 = (const float*)d_in[18];
    const float* pw12 = (const float*)d_in[19];
    const float* pw21 = (const float*)d_in[20];
    const float* pw22 = (const float*)d_in[21];
    float* out = (float*)d_out;

    __nv_bfloat16 *xhi, *xlo, *yhi, *ylo;
    __nv_bfloat16 *qhi, *qlo, *khi, *klo, *vhi, *vlo;
    __nv_bfloat16 *qdhi, *qdlo, *kdhi, *kdlo, *vdhi, *vdlo;
    __nv_bfloat16 *cxhi, *cxlo, *cyhi, *cylo, *whi, *wlo;
    cudaGetSymbolAddress((void**)&xhi,  g_xhi);  cudaGetSymbolAddress((void**)&xlo,  g_xlo);
    cudaGetSymbolAddress((void**)&yhi,  g_yhi);  cudaGetSymbolAddress((void**)&ylo,  g_ylo);
    cudaGetSymbolAddress((void**)&qhi,  g_qhi);  cudaGetSymbolAddress((void**)&qlo,  g_qlo);
    cudaGetSymbolAddress((void**)&khi,  g_khi);  cudaGetSymbolAddress((void**)&klo,  g_klo);
    cudaGetSymbolAddress((void**)&vhi,  g_vhi);  cudaGetSymbolAddress((void**)&vlo,  g_vlo);
    cudaGetSymbolAddress((void**)&qdhi, g_qdhi); cudaGetSymbolAddress((void**)&qdlo, g_qdlo);
    cudaGetSymbolAddress((void**)&kdhi, g_kdhi); cudaGetSymbolAddress((void**)&kdlo, g_kdlo);
    cudaGetSymbolAddress((void**)&vdhi, g_vdhi); cudaGetSymbolAddress((void**)&vdlo, g_vdlo);
    cudaGetSymbolAddress((void**)&cxhi, g_cxhi); cudaGetSymbolAddress((void**)&cxlo, g_cxlo);
    cudaGetSymbolAddress((void**)&cyhi, g_cyhi); cudaGetSymbolAddress((void**)&cylo, g_cylo);
    cudaGetSymbolAddress((void**)&whi,  g_whi);  cudaGetSymbolAddress((void**)&wlo,  g_wlo);

    // splits
    {
        const int n4a = PELEMS / 4, n4w = WN / 4;
        split_bf16<<<(n4a + 255) / 256, 256>>>(hx, xhi, xlo, n4a);
        split_bf16<<<(n4a + 255) / 256, 256>>>(hy, yhi, ylo, n4a);
        for (int i = 0; i < 8; i++)
            split_bf16<<<(n4w + 255) / 256, 256>>>(Wf[i], whi + (size_t)i * WN,
                                                   wlo + (size_t)i * WN, n4w);
    }

    cudaFuncSetAttribute(mm_gemm, cudaFuncAttributeMaxDynamicSharedMemorySize,
                         GEMM_SMEM);
    cudaFuncSetAttribute(attn_mma, cudaFuncAttributeMaxDynamicSharedMemorySize,
                         ATT_SMEM);

    const dim3 gg(PH / 128, PM / 128);   // (6, 64)

    // QKV projections -> bf16 hi/lo planes
    mm_gemm<<<gg, 256, GEMM_SMEM>>>(xhi, xlo, whi + 0 * (size_t)WN, wlo + 0 * (size_t)WN,
                                    Bf[0], nullptr, nullptr, nullptr, qhi, qlo);
    mm_gemm<<<gg, 256, GEMM_SMEM>>>(xhi, xlo, whi + 1 * (size_t)WN, wlo + 1 * (size_t)WN,
                                    Bf[1], nullptr, nullptr, nullptr, khi, klo);
    mm_gemm<<<gg, 256, GEMM_SMEM>>>(xhi, xlo, whi + 2 * (size_t)WN, wlo + 2 * (size_t)WN,
                                    Bf[2], nullptr, nullptr, nullptr, vhi, vlo);
    mm_gemm<<<gg, 256, GEMM_SMEM>>>(yhi, ylo, whi + 4 * (size_t)WN, wlo + 4 * (size_t)WN,
                                    Bf[4], nullptr, nullptr, nullptr, qdhi, qdlo);
    mm_gemm<<<gg, 256, GEMM_SMEM>>>(yhi, ylo, whi + 5 * (size_t)WN, wlo + 5 * (size_t)WN,
                                    Bf[5], nullptr, nullptr, nullptr, kdhi, kdlo);
    mm_gemm<<<gg, 256, GEMM_SMEM>>>(yhi, ylo, whi + 6 * (size_t)WN, wlo + 6 * (size_t)WN,
                                    Bf[6], nullptr, nullptr, nullptr, vdhi, vdlo);

    // dual-stream flash attention -> ctx hi/lo
    const dim3 ga(PS / 64, PNH, PB);
    attn_mma<<<ga, 128, ATT_SMEM>>>(qhi, qlo, khi, klo, vhi, vlo,
                                    kdhi, kdlo, vdhi, vdlo, pw11, pw12, cxhi, cxlo);
    attn_mma<<<ga, 128, ATT_SMEM>>>(qdhi, qdlo, kdhi, kdlo, vdhi, vdlo,
                                    khi, klo, vhi, vlo, pw21, pw22, cyhi, cylo);

    // output projections -> fp32 out (bias scaled by w1+w2)
    mm_gemm<<<gg, 256, GEMM_SMEM>>>(cxhi, cxlo, whi + 3 * (size_t)WN, wlo + 3 * (size_t)WN,
                                    Bf[3], pw11, pw12, out, nullptr, nullptr);
    mm_gemm<<<gg, 256, GEMM_SMEM>>>(cyhi, cylo, whi + 7 * (size_t)WN, wlo + 7 * (size_t)WN,
                                    Bf[7], pw21, pw22, out + (size_t)PM * PH, nullptr, nullptr);
}